// round 6
// baseline (speedup 1.0000x reference)
#include <cuda_runtime.h>
#include <math.h>
#include <stdint.h>

// ---------------------------------------------------------------------------
// BDH forward, all-fp32 with packed f32x2 FMA GEMM engine.
// B=2, T=256, D=256, H=4, n=8192, N=32768, V=32000, L=6
// ---------------------------------------------------------------------------
#define LAYERS 6
#define LN_EPS 1e-5f
#define SCALE_ATTN 0.011048543456039806f   // 1/sqrt(8192)

#define LDA 132                        // smem row stride (words) for 128-wide tiles

// ------------------------- f32x2 helpers -----------------------------------
__device__ __forceinline__ void fma2(uint64_t& d, uint64_t a, uint64_t b) {
    asm("fma.rn.f32x2 %0, %1, %2, %0;" : "+l"(d) : "l"(a), "l"(b));
}
__device__ __forceinline__ uint64_t bcast2(float x) {
    uint64_t r;
    asm("mov.b64 %0, {%1, %1};" : "=l"(r) : "f"(x));
    return r;
}
__device__ __forceinline__ float2 unpk2(uint64_t v) {
    float2 f;
    asm("mov.b64 {%0, %1}, %2;" : "=f"(f.x), "=f"(f.y) : "l"(v));
    return f;
}

// ------------------------- device globals ----------------------------------
__device__ float g_v[512*256];
__device__ float g_lna[512*256];
__device__ __align__(16) float g_x[(size_t)8*256*8192];      // pre-rope x
__device__ __align__(16) float g_y[(size_t)8*256*8192];      // rope(x)
__device__ __align__(16) float g_yflat[(size_t)512*32768];   // y (b,t,N)
__device__ float g_cos[256*4096];
__device__ float g_sin[256*4096];
__device__ __align__(16) float g_sparts[(size_t)8*8*256*256];
__device__ float g_P[2*256*256];
__device__ float g_a[512*256];
__device__ __align__(16) float g_kparts[(size_t)32*512*256];
__device__ float g_z[512*256];

// ------------------------- block reductions --------------------------------
__device__ __forceinline__ float blk_sum256(float v, float* sh) {
#pragma unroll
    for (int o = 16; o > 0; o >>= 1) v += __shfl_xor_sync(0xffffffffu, v, o);
    if ((threadIdx.x & 31) == 0) sh[threadIdx.x >> 5] = v;
    __syncthreads();
    float tot = 0.f;
#pragma unroll
    for (int w = 0; w < 8; w++) tot += sh[w];
    __syncthreads();
    return tot;
}
__device__ __forceinline__ float blk_max256(float v, float* sh) {
#pragma unroll
    for (int o = 16; o > 0; o >>= 1) v = fmaxf(v, __shfl_xor_sync(0xffffffffu, v, o));
    if ((threadIdx.x & 31) == 0) sh[threadIdx.x >> 5] = v;
    __syncthreads();
    float tot = -3.0e38f;
#pragma unroll
    for (int w = 0; w < 8; w++) tot = fmaxf(tot, sh[w]);
    __syncthreads();
    return tot;
}
__device__ __forceinline__ float ln_elem(float x, float* sh) {
    float mean = blk_sum256(x, sh) * (1.f / 256.f);
    float d = x - mean;
    float var = blk_sum256(d * d, sh) * (1.f / 256.f);
    return d * rsqrtf(var + LN_EPS);
}

// ------------------------- small kernels -----------------------------------
__global__ void k_rope_table() {
    int idx = blockIdx.x * 256 + threadIdx.x;
    int i = idx & 4095;
    int t = idx >> 12;
    float ex = (float)(2 * i) * (1.0f / 8192.0f);
    float inv = expf(-9.210340371976184f * ex);
    float f = (float)t * inv;
    float s, c;
    sincosf(f, &s, &c);
    g_cos[idx] = c;
    g_sin[idx] = s;
}

__global__ void k_embed(const int* __restrict__ idx, const float* __restrict__ wte) {
    __shared__ float sh[8];
    int row = blockIdx.x, tid = threadIdx.x;
    int tok = idx[row];
    float x = wte[(size_t)tok * 256 + tid];
    g_v[row * 256 + tid] = ln_elem(x, sh);
}

__global__ void k_softmax() {
    __shared__ float sh[8];
    int row = blockIdx.x;
    int b = row >> 8, t = row & 255;
    int s = threadIdx.x;
    float pacc = 0.f;
    for (int h = 0; h < 4; h++) {
        float val = -3.0e38f;
        if (s <= t) {
            float sum = 0.f;
            int bh = b * 4 + h;
#pragma unroll
            for (int sp = 0; sp < 8; sp++)
                sum += g_sparts[(((size_t)sp * 8 + bh) * 256 + t) * 256 + s];
            val = sum * SCALE_ATTN;
        }
        float mx = blk_max256(val, sh);
        float e = (s <= t) ? expf(val - mx) : 0.f;
        float ssum = blk_sum256(e, sh);
        pacc += e / ssum;
    }
    g_P[(size_t)row * 256 + s] = pacc * 0.25f;
}

// ---- fp32 SIMT tile GEMM for tiny P@V (round-1 proven) ----
__device__ __forceinline__ void load_tile_T64(float dst[16][68], const float* __restrict__ src,
                                              int lda, int tid) {
    int m = tid >> 2, ks = (tid & 3) << 2;
    float4 v = *reinterpret_cast<const float4*>(src + (size_t)m * lda + ks);
    dst[ks + 0][m] = v.x; dst[ks + 1][m] = v.y; dst[ks + 2][m] = v.z; dst[ks + 3][m] = v.w;
}
__device__ __forceinline__ void load_tile_N64(float dst[16][68], const float* __restrict__ src,
                                              int ldb, int tid) {
    int j = tid & 63, k0 = (tid >> 6) << 2;
#pragma unroll
    for (int u = 0; u < 4; u++) dst[k0 + u][j] = src[(size_t)(k0 + u) * ldb + j];
}
__device__ __forceinline__ void mm_tile64(const float As[16][68], const float Bs[16][68],
                                          float acc[4][4], int ty, int tx) {
#pragma unroll
    for (int k = 0; k < 16; k++) {
        float4 a = *reinterpret_cast<const float4*>(&As[k][ty << 2]);
        float4 b = *reinterpret_cast<const float4*>(&Bs[k][tx << 2]);
        float av[4] = {a.x, a.y, a.z, a.w};
        float bv[4] = {b.x, b.y, b.z, b.w};
#pragma unroll
        for (int r = 0; r < 4; r++)
#pragma unroll
            for (int c = 0; c < 4; c++) acc[r][c] = fmaf(av[r], bv[c], acc[r][c]);
    }
}
__global__ void __launch_bounds__(256) k_pv() {
    __shared__ float As[16][68], Bs[16][68];
    int tid = threadIdx.x, tx = tid & 15, ty = tid >> 4;
    int col0 = blockIdx.x << 6, row0 = blockIdx.y << 6, b = blockIdx.z;
    const float* A  = g_P + (size_t)b * 65536;
    const float* Bv = g_v + (size_t)b * 65536;
    float acc[4][4] = {};
    for (int kk = 0; kk < 256; kk += 16) {
        load_tile_T64(As, A + (size_t)row0 * 256 + kk, 256, tid);
        load_tile_N64(Bs, Bv + (size_t)kk * 256 + col0, 256, tid);
        __syncthreads();
        mm_tile64(As, Bs, acc, ty, tx);
        __syncthreads();
    }
#pragma unroll
    for (int r = 0; r < 4; r++) {
        size_t ob = ((size_t)b * 256 + row0 + (ty << 2) + r) * 256 + col0 + (tx << 2);
#pragma unroll
        for (int c = 0; c < 4; c++) g_a[ob + c] = acc[r][c];
    }
}

__global__ void k_ln_a() {
    __shared__ float sh[8];
    int row = blockIdx.x, tid = threadIdx.x;
    float x = g_a[row * 256 + tid];
    g_lna[row * 256 + tid] = ln_elem(x, sh);
}

__global__ void k_reduce() {
    int i = blockIdx.x * 256 + threadIdx.x;
    float s = 0.f;
#pragma unroll
    for (int sp = 0; sp < 32; sp++) s += g_kparts[(size_t)sp * 131072 + i];
    g_z[i] = s;
}

__global__ void k_residual() {
    __shared__ float sh[8];
    int row = blockIdx.x, tid = threadIdx.x;
    float z = g_z[row * 256 + tid];
    float lnz = ln_elem(z, sh);
    float t = g_v[row * 256 + tid] + lnz;
    g_v[row * 256 + tid] = ln_elem(t, sh);
}

// ------------------------- f32x2 GEMM engine --------------------------------
// 128x128 C-tile, BK=16, 256 threads, per-thread 8x8 micro-tile (pairs spread
// by 32 for conflict-free LDS.64). 3-operand packed FMA doubles fp32 rate.
// MODE: 0=dec-x (relu -> g_x, fused rope -> g_y)
//       1=dec-y (relu * g_x -> g_yflat)
//       2=scores (-> g_sparts)   3=enc (-> g_kparts)   4=readout (-> out)
template<int MODE>
__global__ void __launch_bounds__(256, 2) k_mma(const float* __restrict__ Bglob,
                                                float* __restrict__ outp) {
    __shared__ float sA[2][16 * LDA];
    __shared__ float sB[2][16 * LDA];

    const int tid = threadIdx.x;
    const int tx = tid & 15, ty = tid >> 4;

    const float* Asrc;
    const float* Bsrc;
    size_t K;       // A row stride (k-dim length)
    int ldb;        // B row stride for N-layout B (k-major rows)
    int m0, n0, n0b, k0, klen;

    if (MODE == 0 || MODE == 1) {
        Asrc = (MODE == 0) ? g_v : g_lna;
        K = 256; klen = 256; k0 = 0;
        m0 = blockIdx.y << 7;
        n0 = blockIdx.x << 7;
        int hd = n0 >> 13;
        n0b = n0 & 8191;
        Bsrc = Bglob + (size_t)hd * 256 * 8192;
        ldb = 8192;
    } else if (MODE == 2) {
        size_t off = (size_t)blockIdx.y * 256 * 8192;
        Asrc = g_y + off; Bsrc = g_y + off;
        K = 8192; klen = 1024; k0 = blockIdx.z << 10;
        int tp = blockIdx.x;                   // 0:(0,0) 1:(1,0) 2:(1,1)
        m0 = ((tp + 1) >> 1) << 7;
        n0 = (tp >> 1) << 7;
        n0b = n0; ldb = 0;
    } else if (MODE == 3) {
        Asrc = g_yflat; Bsrc = Bglob;
        K = 32768; klen = 1024; k0 = blockIdx.z << 10;
        m0 = blockIdx.y << 7; n0 = blockIdx.x << 7; n0b = n0; ldb = 256;
    } else {
        Asrc = g_v; Bsrc = Bglob;
        K = 256; klen = 256; k0 = 0;
        m0 = blockIdx.y << 7; n0 = blockIdx.x << 7; n0b = n0; ldb = 32000;
    }

    const int total = klen >> 4;   // BK=16 chunks

    // prefetch registers
    float4 pa[2], pb[2];

    // A loader: rows m (k-contiguous), transpose into sA[k][m]
#define LDG_A(c) do {                                                          \
        int _kk = k0 + ((c) << 4);                                             \
        _Pragma("unroll")                                                      \
        for (int j = 0; j < 2; j++) {                                          \
            int u = tid + j * 256;                                             \
            int m = u >> 2, k4 = (u & 3) << 2;                                 \
            pa[j] = *reinterpret_cast<const float4*>(                          \
                Asrc + (size_t)(m0 + m) * K + _kk + k4);                       \
        }                                                                      \
    } while (0)
#define STS_A(buf) do {                                                        \
        _Pragma("unroll")                                                      \
        for (int j = 0; j < 2; j++) {                                          \
            int u = tid + j * 256;                                             \
            int m = u >> 2, k4 = (u & 3) << 2;                                 \
            sA[buf][(k4 + 0) * LDA + m] = pa[j].x;                             \
            sA[buf][(k4 + 1) * LDA + m] = pa[j].y;                             \
            sA[buf][(k4 + 2) * LDA + m] = pa[j].z;                             \
            sA[buf][(k4 + 3) * LDA + m] = pa[j].w;                             \
        }                                                                      \
    } while (0)

    // B loader, two source layouts:
    //  MODE 2: rows n (k-contiguous) -> transpose into sB[k][n]
    //  else:   rows k (n-contiguous) -> direct copy into sB[k][n]
#define LDG_B(c) do {                                                          \
        int _kk = k0 + ((c) << 4);                                             \
        if (MODE == 2) {                                                       \
            _Pragma("unroll")                                                  \
            for (int j = 0; j < 2; j++) {                                      \
                int u = tid + j * 256;                                         \
                int nr = u >> 2, k4 = (u & 3) << 2;                            \
                pb[j] = *reinterpret_cast<const float4*>(                      \
                    Bsrc + (size_t)(n0 + nr) * K + _kk + k4);                  \
            }                                                                  \
        } else {                                                               \
            _Pragma("unroll")                                                  \
            for (int j = 0; j < 2; j++) {                                      \
                int u = tid + j * 256;                                         \
                int kr = u >> 5, nc4 = (u & 31) << 2;                          \
                pb[j] = *reinterpret_cast<const float4*>(                      \
                    Bsrc + (size_t)(_kk + kr) * ldb + n0b + nc4);              \
            }                                                                  \
        }                                                                      \
    } while (0)
#define STS_B(buf) do {                                                        \
        if (MODE == 2) {                                                       \
            _Pragma("unroll")                                                  \
            for (int j = 0; j < 2; j++) {                                      \
                int u = tid + j * 256;                                         \
                int nr = u >> 2, k4 = (u & 3) << 2;                            \
                sB[buf][(k4 + 0) * LDA + nr] = pb[j].x;                        \
                sB[buf][(k4 + 1) * LDA + nr] = pb[j].y;                        \
                sB[buf][(k4 + 2) * LDA + nr] = pb[j].z;                        \
                sB[buf][(k4 + 3) * LDA + nr] = pb[j].w;                        \
            }                                                                  \
        } else {                                                               \
            _Pragma("unroll")                                                  \
            for (int j = 0; j < 2; j++) {                                      \
                int u = tid + j * 256;                                         \
                int kr = u >> 5, nc4 = (u & 31) << 2;                          \
                *reinterpret_cast<float4*>(&sB[buf][kr * LDA + nc4]) = pb[j];  \
            }                                                                  \
        }                                                                      \
    } while (0)

    uint64_t acc[4][4][2];             // [r][c][q] : rows r*32+ty*2+q, cols c*32+tx*2+{0,1}
#pragma unroll
    for (int r = 0; r < 4; r++)
#pragma unroll
        for (int c = 0; c < 4; c++) { acc[r][c][0] = 0ull; acc[r][c][1] = 0ull; }

    LDG_A(0); LDG_B(0);
    STS_A(0); STS_B(0);
    if (total > 1) { LDG_A(1); LDG_B(1); }
    __syncthreads();

    for (int c = 0; c < total; c++) {
        const int buf = c & 1;
        const float* sAb = &sA[buf][0];
        const float* sBb = &sB[buf][0];
#pragma unroll
        for (int k = 0; k < 16; k++) {
            const float* ap = sAb + k * LDA + ty * 2;
            const float* bp = sBb + k * LDA + tx * 2;
            uint64_t bv[4];
#pragma unroll
            for (int cc = 0; cc < 4; cc++)
                bv[cc] = *reinterpret_cast<const uint64_t*>(bp + cc * 32);
#pragma unroll
            for (int r = 0; r < 4; r++) {
                float2 av = *reinterpret_cast<const float2*>(ap + r * 32);
                uint64_t ax = bcast2(av.x), ay = bcast2(av.y);
#pragma unroll
                for (int cc = 0; cc < 4; cc++) {
                    fma2(acc[r][cc][0], ax, bv[cc]);
                    fma2(acc[r][cc][1], ay, bv[cc]);
                }
            }
        }
        if (c + 1 < total) {
            __syncthreads();
            STS_A((c + 1) & 1); STS_B((c + 1) & 1);
            if (c + 2 < total) { LDG_A(c + 2); LDG_B(c + 2); }
            __syncthreads();
        }
    }
#undef LDG_A
#undef STS_A
#undef LDG_B
#undef STS_B

    // ---- epilogue ----
#pragma unroll
    for (int r = 0; r < 4; r++) {
#pragma unroll
        for (int q = 0; q < 2; q++) {
            int row = m0 + r * 32 + ty * 2 + q;
#pragma unroll
            for (int cc = 0; cc < 4; cc++) {
                int col = n0 + cc * 32 + tx * 2;
                float2 val = unpk2(acc[r][cc][q]);
                if (MODE == 0) {
                    int b = row >> 8, t = row & 255;
                    int hd = col >> 13, i = col & 8191;
                    size_t xi = ((size_t)((b << 2) + hd) * 256 + t) * 8192 + i;
                    float xe = fmaxf(val.x, 0.f), xo = fmaxf(val.y, 0.f);
                    *reinterpret_cast<float2*>(&g_x[xi]) = make_float2(xe, xo);
                    int ci = t * 4096 + (i >> 1);
                    float co = g_cos[ci], si = g_sin[ci];
                    *reinterpret_cast<float2*>(&g_y[xi]) =
                        make_float2(xe * co - xo * si, xo * co + xe * si);
                } else if (MODE == 1) {
                    int b = row >> 8, t = row & 255;
                    int hd = col >> 13, i = col & 8191;
                    size_t xi = ((size_t)((b << 2) + hd) * 256 + t) * 8192 + i;
                    float2 xv = *reinterpret_cast<const float2*>(&g_x[xi]);
                    float y0 = fmaxf(val.x, 0.f) * xv.x;
                    float y1 = fmaxf(val.y, 0.f) * xv.y;
                    *reinterpret_cast<float2*>(&g_yflat[(size_t)row * 32768 + col]) =
                        make_float2(y0, y1);
                } else if (MODE == 2) {
                    size_t ob = (((size_t)blockIdx.z * 8 + blockIdx.y) * 256 + row) * 256 + col;
                    *reinterpret_cast<float2*>(&g_sparts[ob]) = val;
                } else if (MODE == 3) {
                    size_t ob = ((size_t)blockIdx.z * 512 + row) * 256 + col;
                    *reinterpret_cast<float2*>(&g_kparts[ob]) = val;
                } else {
                    *reinterpret_cast<float2*>(&outp[(size_t)row * 32000 + col]) = val;
                }
            }
        }
    }
}

// ------------------------- host launcher -----------------------------------
extern "C" void kernel_launch(void* const* d_in, const int* in_sizes, int n_in,
                              void* d_out, int out_size) {
    const int*   idx  = (const int*)d_in[0];
    const float* wte  = (const float*)d_in[1];
    const float* enc  = (const float*)d_in[2];
    const float* decx = (const float*)d_in[3];
    const float* decy = (const float*)d_in[4];
    const float* ro   = (const float*)d_in[5];
    float* out = (float*)d_out;
    (void)in_sizes; (void)n_in; (void)out_size;

    k_rope_table<<<4096, 256>>>();
    k_embed<<<512, 256>>>(idx, wte);

    for (int l = 0; l < LAYERS; l++) {
        k_mma<0><<<dim3(256, 4), 256>>>(decx, nullptr);     // x + fused rope
        k_mma<2><<<dim3(3, 8, 8), 256>>>(nullptr, nullptr); // score partials
        k_softmax<<<512, 256>>>();                          // P = mean_h softmax
        k_pv<<<dim3(4, 4, 2), 256>>>();                     // a = P @ v
        k_ln_a<<<512, 256>>>();                             // lna = ln(a)
        k_mma<1><<<dim3(256, 4), 256>>>(decy, nullptr);     // y = relu(.)*x
        k_mma<3><<<dim3(2, 4, 32), 256>>>(enc, nullptr);    // enc partials
        k_reduce<<<512, 256>>>();                           // z
        k_residual<<<512, 256>>>();                         // v = ln(v+ln(z))
    }

    k_mma<4><<<dim3(250, 4), 256>>>(ro, out);               // logits
}

// round 7
// speedup vs baseline: 1.2194x; 1.2194x over previous
#include <cuda_runtime.h>
#include <math.h>
#include <stdint.h>

// ---------------------------------------------------------------------------
// BDH forward, all-fp32, packed f32x2 GEMM engine v2 (dup-A smem, 8x4 micro).
// B=2, T=256, D=256, H=4, n=8192, N=32768, V=32000, L=6
// ---------------------------------------------------------------------------
#define LAYERS 6
#define LN_EPS 1e-5f
#define SCALE_ATTN 0.011048543456039806f   // 1/sqrt(8192)

#define LDA2 130     // A smem row stride in u64 (128 data + pad)
#define LDB  68      // B smem row stride in f32 (64 data + pad)

// ------------------------- f32x2 helpers -----------------------------------
__device__ __forceinline__ void fma2(uint64_t& d, uint64_t a, uint64_t b) {
    asm("fma.rn.f32x2 %0, %1, %2, %0;" : "+l"(d) : "l"(a), "l"(b));
}
__device__ __forceinline__ uint64_t dup2(float x) {
    uint64_t r;
    asm("mov.b64 %0, {%1, %1};" : "=l"(r) : "f"(x));
    return r;
}
__device__ __forceinline__ float2 unpk2(uint64_t v) {
    float2 f;
    asm("mov.b64 {%0, %1}, %2;" : "=f"(f.x), "=f"(f.y) : "l"(v));
    return f;
}

// ------------------------- device globals ----------------------------------
__device__ float g_v[512*256];
__device__ float g_lna[512*256];
__device__ __align__(16) float g_x[(size_t)8*256*8192];      // pre-rope x
__device__ __align__(16) float g_y[(size_t)8*256*8192];      // rope(x)
__device__ __align__(16) float g_yflat[(size_t)512*32768];   // y (b,t,N)
__device__ float g_cos[256*4096];
__device__ float g_sin[256*4096];
__device__ __align__(16) float g_sparts[(size_t)16*8*256*256];
__device__ float g_P[2*256*256];
__device__ float g_a[512*256];
__device__ __align__(16) float g_kparts[(size_t)64*512*256];
__device__ float g_z[512*256];

// ------------------------- block reductions --------------------------------
__device__ __forceinline__ float blk_sum256(float v, float* sh) {
#pragma unroll
    for (int o = 16; o > 0; o >>= 1) v += __shfl_xor_sync(0xffffffffu, v, o);
    if ((threadIdx.x & 31) == 0) sh[threadIdx.x >> 5] = v;
    __syncthreads();
    float tot = 0.f;
#pragma unroll
    for (int w = 0; w < 8; w++) tot += sh[w];
    __syncthreads();
    return tot;
}
__device__ __forceinline__ float blk_max256(float v, float* sh) {
#pragma unroll
    for (int o = 16; o > 0; o >>= 1) v = fmaxf(v, __shfl_xor_sync(0xffffffffu, v, o));
    if ((threadIdx.x & 31) == 0) sh[threadIdx.x >> 5] = v;
    __syncthreads();
    float tot = -3.0e38f;
#pragma unroll
    for (int w = 0; w < 8; w++) tot = fmaxf(tot, sh[w]);
    __syncthreads();
    return tot;
}
__device__ __forceinline__ float ln_elem(float x, float* sh) {
    float mean = blk_sum256(x, sh) * (1.f / 256.f);
    float d = x - mean;
    float var = blk_sum256(d * d, sh) * (1.f / 256.f);
    return d * rsqrtf(var + LN_EPS);
}

// ------------------------- small kernels -----------------------------------
__global__ void k_rope_table() {
    int idx = blockIdx.x * 256 + threadIdx.x;
    int i = idx & 4095;
    int t = idx >> 12;
    float ex = (float)(2 * i) * (1.0f / 8192.0f);
    float inv = expf(-9.210340371976184f * ex);
    float f = (float)t * inv;
    float s, c;
    sincosf(f, &s, &c);
    g_cos[idx] = c;
    g_sin[idx] = s;
}

__global__ void k_embed(const int* __restrict__ idx, const float* __restrict__ wte) {
    __shared__ float sh[8];
    int row = blockIdx.x, tid = threadIdx.x;
    int tok = idx[row];
    float x = wte[(size_t)tok * 256 + tid];
    g_v[row * 256 + tid] = ln_elem(x, sh);
}

__global__ void k_softmax() {
    __shared__ float sh[8];
    int row = blockIdx.x;
    int b = row >> 8, t = row & 255;
    int s = threadIdx.x;
    float pacc = 0.f;
    for (int h = 0; h < 4; h++) {
        float val = -3.0e38f;
        if (s <= t) {
            float sum = 0.f;
            int bh = b * 4 + h;
#pragma unroll
            for (int sp = 0; sp < 16; sp++)
                sum += g_sparts[(((size_t)sp * 8 + bh) * 256 + t) * 256 + s];
            val = sum * SCALE_ATTN;
        }
        float mx = blk_max256(val, sh);
        float e = (s <= t) ? expf(val - mx) : 0.f;
        float ssum = blk_sum256(e, sh);
        pacc += e / ssum;
    }
    g_P[(size_t)row * 256 + s] = pacc * 0.25f;
}

// ---- fp32 SIMT tile GEMM for tiny P@V (round-1 proven) ----
__device__ __forceinline__ void load_tile_T64(float dst[16][68], const float* __restrict__ src,
                                              int lda, int tid) {
    int m = tid >> 2, ks = (tid & 3) << 2;
    float4 v = *reinterpret_cast<const float4*>(src + (size_t)m * lda + ks);
    dst[ks + 0][m] = v.x; dst[ks + 1][m] = v.y; dst[ks + 2][m] = v.z; dst[ks + 3][m] = v.w;
}
__device__ __forceinline__ void load_tile_N64(float dst[16][68], const float* __restrict__ src,
                                              int ldb, int tid) {
    int j = tid & 63, k0 = (tid >> 6) << 2;
#pragma unroll
    for (int u = 0; u < 4; u++) dst[k0 + u][j] = src[(size_t)(k0 + u) * ldb + j];
}
__device__ __forceinline__ void mm_tile64(const float As[16][68], const float Bs[16][68],
                                          float acc[4][4], int ty, int tx) {
#pragma unroll
    for (int k = 0; k < 16; k++) {
        float4 a = *reinterpret_cast<const float4*>(&As[k][ty << 2]);
        float4 b = *reinterpret_cast<const float4*>(&Bs[k][tx << 2]);
        float av[4] = {a.x, a.y, a.z, a.w};
        float bv[4] = {b.x, b.y, b.z, b.w};
#pragma unroll
        for (int r = 0; r < 4; r++)
#pragma unroll
            for (int c = 0; c < 4; c++) acc[r][c] = fmaf(av[r], bv[c], acc[r][c]);
    }
}
__global__ void __launch_bounds__(256) k_pv() {
    __shared__ float As[16][68], Bs[16][68];
    int tid = threadIdx.x, tx = tid & 15, ty = tid >> 4;
    int col0 = blockIdx.x << 6, row0 = blockIdx.y << 6, b = blockIdx.z;
    const float* A  = g_P + (size_t)b * 65536;
    const float* Bv = g_v + (size_t)b * 65536;
    float acc[4][4] = {};
    for (int kk = 0; kk < 256; kk += 16) {
        load_tile_T64(As, A + (size_t)row0 * 256 + kk, 256, tid);
        load_tile_N64(Bs, Bv + (size_t)kk * 256 + col0, 256, tid);
        __syncthreads();
        mm_tile64(As, Bs, acc, ty, tx);
        __syncthreads();
    }
#pragma unroll
    for (int r = 0; r < 4; r++) {
        size_t ob = ((size_t)b * 256 + row0 + (ty << 2) + r) * 256 + col0 + (tx << 2);
#pragma unroll
        for (int c = 0; c < 4; c++) g_a[ob + c] = acc[r][c];
    }
}

__global__ void k_ln_a() {
    __shared__ float sh[8];
    int row = blockIdx.x, tid = threadIdx.x;
    float x = g_a[row * 256 + tid];
    g_lna[row * 256 + tid] = ln_elem(x, sh);
}

__global__ void k_reduce() {
    int i = blockIdx.x * 256 + threadIdx.x;
    float s = 0.f;
#pragma unroll
    for (int sp = 0; sp < 64; sp++) s += g_kparts[(size_t)sp * 131072 + i];
    g_z[i] = s;
}

__global__ void k_residual() {
    __shared__ float sh[8];
    int row = blockIdx.x, tid = threadIdx.x;
    float z = g_z[row * 256 + tid];
    float lnz = ln_elem(z, sh);
    float t = g_v[row * 256 + tid] + lnz;
    g_v[row * 256 + tid] = ln_elem(t, sh);
}

// ------------------------- f32x2 GEMM engine v2 ------------------------------
// 128x64 C-tile, BK=16, 256 threads (8 warps, 4m x 2n), warp tile 32x32,
// per-thread micro 8m x 4n. A stored DUPLICATED in smem as (a,a) u64 pairs ->
// inner loop: 4x LDS.128 (A) + 1x LDS.128 (B) + 16 FFMA2, no movs.
// MODE: 0=dec-x (relu -> g_x, fused rope -> g_y)
//       1=dec-y (relu * g_x -> g_yflat)
//       2=scores (-> g_sparts)   3=enc (-> g_kparts)   4=readout (-> out)
template<int MODE>
__global__ void __launch_bounds__(256, 2) k_mma(const float* __restrict__ Bglob,
                                                float* __restrict__ outp) {
    __shared__ __align__(16) uint64_t sA2[2][16 * LDA2];
    __shared__ __align__(16) float    sBs[2][16 * LDB];

    const int tid = threadIdx.x;
    const int warp = tid >> 5, lane = tid & 31;
    const int warp_m = warp & 3, warp_n = warp >> 2;
    const int tr = lane >> 3, tc = lane & 7;
    const int aoff = warp_m * 32 + tr * 8;      // u64 units within a k-row
    const int boff = warp_n * 32 + tc * 4;      // f32 units within a k-row

    const float* Asrc;
    const float* Bsrc;
    size_t K;       // A row k-length
    int ldb;        // B row stride (k-major rows); 0 => B is k-contiguous rows (mode 2)
    int m0, n0, n0b, k0, klen;

    if (MODE == 0 || MODE == 1) {
        Asrc = (MODE == 0) ? g_v : g_lna;
        K = 256; klen = 256; k0 = 0;
        m0 = blockIdx.y << 7;
        n0 = blockIdx.x << 6;
        int hd = n0 >> 13;
        n0b = n0 & 8191;
        Bsrc = Bglob + (size_t)hd * 256 * 8192;
        ldb = 8192;
    } else if (MODE == 2) {
        const int TM[6] = {0,0,1,1,1,1};
        const int TN[6] = {0,1,0,1,2,3};
        size_t off = (size_t)blockIdx.y * 256 * 8192;
        Asrc = g_y + off; Bsrc = g_y + off;
        K = 8192; klen = 512; k0 = blockIdx.z << 9;
        m0 = TM[blockIdx.x] << 7;
        n0 = TN[blockIdx.x] << 6;
        n0b = n0; ldb = 0;
    } else if (MODE == 3) {
        Asrc = g_yflat; Bsrc = Bglob;
        K = 32768; klen = 512; k0 = blockIdx.z << 9;
        m0 = blockIdx.y << 7; n0 = blockIdx.x << 6; n0b = n0; ldb = 256;
    } else {
        Asrc = g_v; Bsrc = Bglob;
        K = 256; klen = 256; k0 = 0;
        m0 = blockIdx.y << 7; n0 = blockIdx.x << 6; n0b = n0; ldb = 32000;
    }

    const int total = klen >> 4;   // BK=16 chunks

    float4 pa[2], pb;

    // A: rows m (k-contiguous). 128 rows x 16 k = 512 float4, 2 per thread.
#define LDG_A(c) do {                                                          \
        int _kk = k0 + ((c) << 4);                                             \
        _Pragma("unroll")                                                      \
        for (int j = 0; j < 2; j++) {                                          \
            int u = tid + j * 256;                                             \
            int m = u >> 2, k4 = (u & 3) << 2;                                 \
            pa[j] = *reinterpret_cast<const float4*>(                          \
                Asrc + (size_t)(m0 + m) * K + _kk + k4);                       \
        }                                                                      \
    } while (0)
    // store transposed + duplicated: sA2[k][m] = (a,a)
#define STS_A(buf) do {                                                        \
        _Pragma("unroll")                                                      \
        for (int j = 0; j < 2; j++) {                                          \
            int u = tid + j * 256;                                             \
            int m = u >> 2, k4 = (u & 3) << 2;                                 \
            sA2[buf][(k4 + 0) * LDA2 + m] = dup2(pa[j].x);                     \
            sA2[buf][(k4 + 1) * LDA2 + m] = dup2(pa[j].y);                     \
            sA2[buf][(k4 + 2) * LDA2 + m] = dup2(pa[j].z);                     \
            sA2[buf][(k4 + 3) * LDA2 + m] = dup2(pa[j].w);                     \
        }                                                                      \
    } while (0)

    // B: 64 n x 16 k tile.
#define LDG_B(c) do {                                                          \
        int _kk = k0 + ((c) << 4);                                             \
        if (MODE == 2) {                                                       \
            int nr = tid >> 2, k4 = (tid & 3) << 2;                            \
            pb = *reinterpret_cast<const float4*>(                             \
                Bsrc + (size_t)(n0 + nr) * K + _kk + k4);                      \
        } else {                                                               \
            int kr = tid >> 4, nc4 = (tid & 15) << 2;                          \
            pb = *reinterpret_cast<const float4*>(                             \
                Bsrc + (size_t)(_kk + kr) * ldb + n0b + nc4);                  \
        }                                                                      \
    } while (0)
#define STS_B(buf) do {                                                        \
        if (MODE == 2) {                                                       \
            int nr = tid >> 2, k4 = (tid & 3) << 2;                            \
            sBs[buf][(k4 + 0) * LDB + nr] = pb.x;                              \
            sBs[buf][(k4 + 1) * LDB + nr] = pb.y;                              \
            sBs[buf][(k4 + 2) * LDB + nr] = pb.z;                              \
            sBs[buf][(k4 + 3) * LDB + nr] = pb.w;                              \
        } else {                                                               \
            int kr = tid >> 4, nc4 = (tid & 15) << 2;                          \
            *reinterpret_cast<float4*>(&sBs[buf][kr * LDB + nc4]) = pb;        \
        }                                                                      \
    } while (0)

    uint64_t acc[8][2];                // [i m-row][j n-pair] : 16 u64 = 32 regs
#pragma unroll
    for (int i = 0; i < 8; i++) { acc[i][0] = 0ull; acc[i][1] = 0ull; }

    LDG_A(0); LDG_B(0);
    STS_A(0); STS_B(0);
    if (total > 1) { LDG_A(1); LDG_B(1); }
    __syncthreads();

    for (int c = 0; c < total; c++) {
        const int buf = c & 1;
#pragma unroll
        for (int k = 0; k < 16; k++) {
            const ulonglong2* ap =
                reinterpret_cast<const ulonglong2*>(&sA2[buf][k * LDA2 + aoff]);
            ulonglong2 a0 = ap[0], a1 = ap[1], a2v = ap[2], a3v = ap[3];
            ulonglong2 b =
                *reinterpret_cast<const ulonglong2*>(&sBs[buf][k * LDB + boff]);
            fma2(acc[0][0], a0.x, b.x);  fma2(acc[0][1], a0.x, b.y);
            fma2(acc[1][0], a0.y, b.x);  fma2(acc[1][1], a0.y, b.y);
            fma2(acc[2][0], a1.x, b.x);  fma2(acc[2][1], a1.x, b.y);
            fma2(acc[3][0], a1.y, b.x);  fma2(acc[3][1], a1.y, b.y);
            fma2(acc[4][0], a2v.x, b.x); fma2(acc[4][1], a2v.x, b.y);
            fma2(acc[5][0], a2v.y, b.x); fma2(acc[5][1], a2v.y, b.y);
            fma2(acc[6][0], a3v.x, b.x); fma2(acc[6][1], a3v.x, b.y);
            fma2(acc[7][0], a3v.y, b.x); fma2(acc[7][1], a3v.y, b.y);
        }
        if (c + 1 < total) {
            __syncthreads();
            STS_A((c + 1) & 1); STS_B((c + 1) & 1);
            if (c + 2 < total) { LDG_A(c + 2); LDG_B(c + 2); }
            __syncthreads();
        }
    }
#undef LDG_A
#undef STS_A
#undef LDG_B
#undef STS_B

    // ---- epilogue ----
#pragma unroll
    for (int i = 0; i < 8; i++) {
        int row = m0 + warp_m * 32 + tr * 8 + i;
#pragma unroll
        for (int j = 0; j < 2; j++) {
            int col = n0 + warp_n * 32 + tc * 4 + j * 2;
            float2 val = unpk2(acc[i][j]);
            if (MODE == 0) {
                int b = row >> 8, t = row & 255;
                int hd = col >> 13, ii = col & 8191;
                size_t xi = ((size_t)((b << 2) + hd) * 256 + t) * 8192 + ii;
                float xe = fmaxf(val.x, 0.f), xo = fmaxf(val.y, 0.f);
                *reinterpret_cast<float2*>(&g_x[xi]) = make_float2(xe, xo);
                int ci = t * 4096 + (ii >> 1);
                float co = g_cos[ci], si = g_sin[ci];
                *reinterpret_cast<float2*>(&g_y[xi]) =
                    make_float2(xe * co - xo * si, xo * co + xe * si);
            } else if (MODE == 1) {
                int b = row >> 8, t = row & 255;
                int hd = col >> 13, ii = col & 8191;
                size_t xi = ((size_t)((b << 2) + hd) * 256 + t) * 8192 + ii;
                float2 xv = *reinterpret_cast<const float2*>(&g_x[xi]);
                float y0 = fmaxf(val.x, 0.f) * xv.x;
                float y1 = fmaxf(val.y, 0.f) * xv.y;
                *reinterpret_cast<float2*>(&g_yflat[(size_t)row * 32768 + col]) =
                    make_float2(y0, y1);
            } else if (MODE == 2) {
                size_t ob = (((size_t)blockIdx.z * 8 + blockIdx.y) * 256 + row) * 256 + col;
                *reinterpret_cast<float2*>(&g_sparts[ob]) = val;
            } else if (MODE == 3) {
                size_t ob = ((size_t)blockIdx.z * 512 + row) * 256 + col;
                *reinterpret_cast<float2*>(&g_kparts[ob]) = val;
            } else {
                *reinterpret_cast<float2*>(&outp[(size_t)row * 32000 + col]) = val;
            }
        }
    }
}

// ------------------------- host launcher -----------------------------------
extern "C" void kernel_launch(void* const* d_in, const int* in_sizes, int n_in,
                              void* d_out, int out_size) {
    const int*   idx  = (const int*)d_in[0];
    const float* wte  = (const float*)d_in[1];
    const float* enc  = (const float*)d_in[2];
    const float* decx = (const float*)d_in[3];
    const float* decy = (const float*)d_in[4];
    const float* ro   = (const float*)d_in[5];
    float* out = (float*)d_out;
    (void)in_sizes; (void)n_in; (void)out_size;

    k_rope_table<<<4096, 256>>>();
    k_embed<<<512, 256>>>(idx, wte);

    for (int l = 0; l < LAYERS; l++) {
        k_mma<0><<<dim3(512, 4), 256>>>(decx, nullptr);      // x + fused rope
        k_mma<2><<<dim3(6, 8, 16), 256>>>(nullptr, nullptr); // score partials
        k_softmax<<<512, 256>>>();                           // P = mean_h softmax
        k_pv<<<dim3(4, 4, 2), 256>>>();                      // a = P @ v
        k_ln_a<<<512, 256>>>();                              // lna = ln(a)
        k_mma<1><<<dim3(512, 4), 256>>>(decy, nullptr);      // y = relu(.)*x
        k_mma<3><<<dim3(4, 4, 64), 256>>>(enc, nullptr);     // enc partials
        k_reduce<<<512, 256>>>();                            // z
        k_residual<<<512, 256>>>();                          // v = ln(v+ln(z))
    }

    k_mma<4><<<dim3(500, 4), 256>>>(ro, out);                // logits
}

// round 8
// speedup vs baseline: 2.0595x; 1.6889x over previous
#include <cuda_runtime.h>
#include <cuda_bf16.h>
#include <math.h>
#include <stdint.h>

// ---------------------------------------------------------------------------
// BDH forward. GEMMs = bf16 hi/lo 3-pass (3xBF16) warp-tiled HMMA (mma.sync),
// conservative engine. FIX vs round 5: no __device__ symbols passed from host
// (that passed host-shadow addresses; ATS made writes land in host memory
// silently, leaving the real device weight arrays zero).
// B=2,T=256,D=256,H=4,n=8192,N=32768,V=32000,L=6
// ---------------------------------------------------------------------------
#define LAYERS 6
#define LN_EPS 1e-5f
#define SCALE_ATTN 0.011048543456039806f   // 1/sqrt(8192)

#define ROWE 40                 // smem row stride in bf16 elements (80 bytes)

__device__ __forceinline__ void mma16816(float d[4], const uint32_t a[4],
                                         uint32_t b0, uint32_t b1) {
    asm volatile(
        "mma.sync.aligned.m16n8k16.row.col.f32.bf16.bf16.f32 "
        "{%0,%1,%2,%3}, {%4,%5,%6,%7}, {%8,%9}, {%0,%1,%2,%3};"
        : "+f"(d[0]), "+f"(d[1]), "+f"(d[2]), "+f"(d[3])
        : "r"(a[0]), "r"(a[1]), "r"(a[2]), "r"(a[3]), "r"(b0), "r"(b1));
}

// ------------------------- device globals ----------------------------------
__device__ float g_v[512*256];
__device__ __align__(16) float g_x[(size_t)8*256*8192];   // (b*4+h, t, i)
__device__ float g_cos[256*4096];
__device__ float g_sin[256*4096];
__device__ __align__(16) float g_sparts[(size_t)8*8*256*256];  // 8 splits
__device__ float g_P[2*256*256];
__device__ float g_a[512*256];
__device__ __align__(16) float g_kparts[(size_t)32*512*256];
__device__ float g_z[512*256];

__device__ __align__(16) __nv_bfloat16 v_h[512*256],   v_l[512*256];
__device__ __align__(16) __nv_bfloat16 lna_h[512*256], lna_l[512*256];
__device__ __align__(16) __nv_bfloat16 xr_h[(size_t)8*256*8192];
__device__ __align__(16) __nv_bfloat16 xr_l[(size_t)8*256*8192];
__device__ __align__(16) __nv_bfloat16 y_h[(size_t)512*32768];
__device__ __align__(16) __nv_bfloat16 y_l[(size_t)512*32768];
__device__ __align__(16) __nv_bfloat16 dxt_h[(size_t)32768*256];
__device__ __align__(16) __nv_bfloat16 dxt_l[(size_t)32768*256];
__device__ __align__(16) __nv_bfloat16 dyt_h[(size_t)32768*256];
__device__ __align__(16) __nv_bfloat16 dyt_l[(size_t)32768*256];
__device__ __align__(16) __nv_bfloat16 et_h[(size_t)256*32768];
__device__ __align__(16) __nv_bfloat16 et_l[(size_t)256*32768];
__device__ __align__(16) __nv_bfloat16 rt_h[(size_t)32000*256];
__device__ __align__(16) __nv_bfloat16 rt_l[(size_t)32000*256];

__device__ __forceinline__ void bf16split(float v, __nv_bfloat16& h, __nv_bfloat16& l) {
    h = __float2bfloat16(v);
    l = __float2bfloat16(v - __bfloat162float(h));
}

// ------------------------- block reductions --------------------------------
__device__ __forceinline__ float blk_sum256(float v, float* sh) {
#pragma unroll
    for (int o = 16; o > 0; o >>= 1) v += __shfl_xor_sync(0xffffffffu, v, o);
    if ((threadIdx.x & 31) == 0) sh[threadIdx.x >> 5] = v;
    __syncthreads();
    float tot = 0.f;
#pragma unroll
    for (int w = 0; w < 8; w++) tot += sh[w];
    __syncthreads();
    return tot;
}
__device__ __forceinline__ float blk_max256(float v, float* sh) {
#pragma unroll
    for (int o = 16; o > 0; o >>= 1) v = fmaxf(v, __shfl_xor_sync(0xffffffffu, v, o));
    if ((threadIdx.x & 31) == 0) sh[threadIdx.x >> 5] = v;
    __syncthreads();
    float tot = -3.0e38f;
#pragma unroll
    for (int w = 0; w < 8; w++) tot = fmaxf(tot, sh[w]);
    __syncthreads();
    return tot;
}
__device__ __forceinline__ float ln_elem(float x, float* sh) {
    float mean = blk_sum256(x, sh) * (1.f / 256.f);
    float d = x - mean;
    float var = blk_sum256(d * d, sh) * (1.f / 256.f);
    return d * rsqrtf(var + LN_EPS);
}

// ------------------------- small kernels -----------------------------------
__global__ void k_rope_table() {
    int idx = blockIdx.x * 256 + threadIdx.x;
    int i = idx & 4095;
    int t = idx >> 12;
    float ex = (float)(2 * i) * (1.0f / 8192.0f);
    float inv = expf(-9.210340371976184f * ex);
    float f = (float)t * inv;
    float s, c;
    sincosf(f, &s, &c);
    g_cos[idx] = c;
    g_sin[idx] = s;
}

__global__ void k_embed(const int* __restrict__ idx, const float* __restrict__ wte) {
    __shared__ float sh[8];
    int row = blockIdx.x, tid = threadIdx.x;
    int tok = idx[row];
    float x = wte[(size_t)tok * 256 + tid];
    float r = ln_elem(x, sh);
    g_v[row * 256 + tid] = r;
    __nv_bfloat16 h, l; bf16split(r, h, l);
    v_h[row * 256 + tid] = h; v_l[row * 256 + tid] = l;
}

// transpose + bf16 hi/lo: out[c*R + r] = in[r*C + c]
// DST selects the destination device arrays IN-KERNEL (the round-3..5 bug was
// passing these __device__ symbols from host code).
template<int DST>
__global__ void k_tcvt(const float* __restrict__ in, int R, int C,
                       size_t in_z, size_t out_z) {
    __shared__ float tile[32][33];
    __nv_bfloat16* oh;
    __nv_bfloat16* ol;
    if (DST == 0) { oh = dxt_h; ol = dxt_l; }
    else if (DST == 1) { oh = dyt_h; ol = dyt_l; }
    else if (DST == 2) { oh = et_h; ol = et_l; }
    else { oh = rt_h; ol = rt_l; }
    int z = blockIdx.z;
    const float* src = in + (size_t)z * in_z;
    __nv_bfloat16* dh = oh + (size_t)z * out_z;
    __nv_bfloat16* dl = ol + (size_t)z * out_z;
    int r0 = blockIdx.y * 32, c0 = blockIdx.x * 32;
    for (int i = threadIdx.y; i < 32; i += 8)
        tile[i][threadIdx.x] = src[(size_t)(r0 + i) * C + c0 + threadIdx.x];
    __syncthreads();
    for (int i = threadIdx.y; i < 32; i += 8) {
        float v = tile[threadIdx.x][i];
        __nv_bfloat16 h, l; bf16split(v, h, l);
        size_t o = (size_t)(c0 + i) * R + r0 + threadIdx.x;
        dh[o] = h; dl[o] = l;
    }
}

__global__ void k_softmax() {
    __shared__ float sh[8];
    int row = blockIdx.x;
    int b = row >> 8, t = row & 255;
    int s = threadIdx.x;
    float pacc = 0.f;
    for (int h = 0; h < 4; h++) {
        float val = -3.0e38f;
        if (s <= t) {
            float sum = 0.f;
            int bh = b * 4 + h;
#pragma unroll
            for (int sp = 0; sp < 8; sp++)
                sum += g_sparts[(((size_t)sp * 8 + bh) * 256 + t) * 256 + s];
            val = sum * SCALE_ATTN;
        }
        float mx = blk_max256(val, sh);
        float e = (s <= t) ? expf(val - mx) : 0.f;
        float ssum = blk_sum256(e, sh);
        pacc += e / ssum;
    }
    g_P[(size_t)row * 256 + s] = pacc * 0.25f;
}

// ---- fp32 SIMT tile GEMM kept for tiny P@V ----
__device__ __forceinline__ void load_tile_T(float dst[16][68], const float* __restrict__ src,
                                            int lda, int tid) {
    int m = tid >> 2, ks = (tid & 3) << 2;
    float4 v = *reinterpret_cast<const float4*>(src + (size_t)m * lda + ks);
    dst[ks + 0][m] = v.x; dst[ks + 1][m] = v.y; dst[ks + 2][m] = v.z; dst[ks + 3][m] = v.w;
}
__device__ __forceinline__ void load_tile_N(float dst[16][68], const float* __restrict__ src,
                                            int ldb, int tid) {
    int j = tid & 63, k0 = (tid >> 6) << 2;
#pragma unroll
    for (int u = 0; u < 4; u++) dst[k0 + u][j] = src[(size_t)(k0 + u) * ldb + j];
}
__device__ __forceinline__ void mm_tile(const float As[16][68], const float Bs[16][68],
                                        float acc[4][4], int ty, int tx) {
#pragma unroll
    for (int k = 0; k < 16; k++) {
        float4 a = *reinterpret_cast<const float4*>(&As[k][ty << 2]);
        float4 b = *reinterpret_cast<const float4*>(&Bs[k][tx << 2]);
        float av[4] = {a.x, a.y, a.z, a.w};
        float bv[4] = {b.x, b.y, b.z, b.w};
#pragma unroll
        for (int r = 0; r < 4; r++)
#pragma unroll
            for (int c = 0; c < 4; c++) acc[r][c] = fmaf(av[r], bv[c], acc[r][c]);
    }
}
__global__ void __launch_bounds__(256) k_pv() {
    __shared__ float As[16][68], Bs[16][68];
    int tid = threadIdx.x, tx = tid & 15, ty = tid >> 4;
    int col0 = blockIdx.x << 6, row0 = blockIdx.y << 6, b = blockIdx.z;
    const float* A  = g_P + (size_t)b * 65536;
    const float* Bv = g_v + (size_t)b * 65536;
    float acc[4][4] = {};
    for (int kk = 0; kk < 256; kk += 16) {
        load_tile_T(As, A + (size_t)row0 * 256 + kk, 256, tid);
        load_tile_N(Bs, Bv + (size_t)kk * 256 + col0, 256, tid);
        __syncthreads();
        mm_tile(As, Bs, acc, ty, tx);
        __syncthreads();
    }
#pragma unroll
    for (int r = 0; r < 4; r++) {
        size_t ob = ((size_t)b * 256 + row0 + (ty << 2) + r) * 256 + col0 + (tx << 2);
#pragma unroll
        for (int c = 0; c < 4; c++) g_a[ob + c] = acc[r][c];
    }
}

__global__ void k_ln_a() {
    __shared__ float sh[8];
    int row = blockIdx.x, tid = threadIdx.x;
    float x = g_a[row * 256 + tid];
    float r = ln_elem(x, sh);
    __nv_bfloat16 h, l; bf16split(r, h, l);
    lna_h[row * 256 + tid] = h; lna_l[row * 256 + tid] = l;
}

__global__ void k_reduce() {
    int i = blockIdx.x * 256 + threadIdx.x;
    float s = 0.f;
#pragma unroll
    for (int sp = 0; sp < 32; sp++) s += g_kparts[(size_t)sp * 131072 + i];
    g_z[i] = s;
}

__global__ void k_residual() {
    __shared__ float sh[8];
    int row = blockIdx.x, tid = threadIdx.x;
    float z = g_z[row * 256 + tid];
    float lnz = ln_elem(z, sh);
    float t = g_v[row * 256 + tid] + lnz;
    float r = ln_elem(t, sh);
    g_v[row * 256 + tid] = r;
    __nv_bfloat16 h, l; bf16split(r, h, l);
    v_h[row * 256 + tid] = h; v_l[row * 256 + tid] = l;
}

// ------------------------- HMMA GEMM (conservative engine) ------------------
// MODE: 0=dec-x (relu -> g_x + fused rope -> xr hi/lo)
//       1=dec-y (relu * g_x -> y hi/lo)
//       2=scores (fp32 -> g_sparts)   3=enc (fp32 -> g_kparts)
//       4=readout (fp32 -> out)
// 128x128 tile, BK=32 (2 k-steps), 8 warps (2m x 4n), warp tile 64x32.
template<int MODE>
__global__ void __launch_bounds__(256) k_mma(float* __restrict__ outp) {
    __shared__ __align__(16) __nv_bfloat16 sA[2][128 * ROWE];
    __shared__ __align__(16) __nv_bfloat16 sB[2][128 * ROWE];

    int tid = threadIdx.x;
    int wid = tid >> 5, lane = tid & 31;
    int warp_m = wid & 1, warp_n = wid >> 1;
    int gid = lane >> 2, tig = lane & 3;

    const __nv_bfloat16 *Ah, *Al, *Bh, *Bl;
    size_t K;
    int m0, n0, k0, klen;
    if (MODE == 0) {
        Ah = v_h; Al = v_l; Bh = dxt_h; Bl = dxt_l;
        K = 256; m0 = blockIdx.y << 7; n0 = blockIdx.x << 7; k0 = 0; klen = 256;
    } else if (MODE == 1) {
        Ah = lna_h; Al = lna_l; Bh = dyt_h; Bl = dyt_l;
        K = 256; m0 = blockIdx.y << 7; n0 = blockIdx.x << 7; k0 = 0; klen = 256;
    } else if (MODE == 2) {
        size_t off = (size_t)blockIdx.y * 256 * 8192;
        Ah = xr_h + off; Al = xr_l + off; Bh = Ah; Bl = Al;
        K = 8192;
        int tp = blockIdx.x;
        m0 = ((tp + 1) >> 1) << 7; n0 = (tp >> 1) << 7;
        k0 = blockIdx.z << 10; klen = 1024;
    } else if (MODE == 3) {
        Ah = y_h; Al = y_l; Bh = et_h; Bl = et_l;
        K = 32768; m0 = blockIdx.y << 7; n0 = blockIdx.x << 7;
        k0 = blockIdx.z << 10; klen = 1024;
    } else {
        Ah = v_h; Al = v_l; Bh = rt_h; Bl = rt_l;
        K = 256; m0 = blockIdx.y << 7; n0 = blockIdx.x << 7; k0 = 0; klen = 256;
    }

    const int cpp = klen >> 5;          // 32-k chunks per pass
    const int total = 3 * cpp;

    // per-thread LDG/STS geometry: rows r and r+64, 16B column chunk c16
    const int r = tid >> 2, c16 = tid & 3;
    uint4 pa0, pa1, pb0, pb1;

#define LDG_CHUNK(c) do {                                                     \
        int _pass = (c) / cpp;                                                \
        int _kk = k0 + (((c) - _pass * cpp) << 5);                            \
        const __nv_bfloat16* _As = (_pass < 2) ? Ah : Al;                     \
        const __nv_bfloat16* _Bs = (_pass == 0) ? Bh : ((_pass == 1) ? Bl : Bh); \
        pa0 = *reinterpret_cast<const uint4*>(_As + (size_t)(m0 + r) * K + _kk + c16 * 8);       \
        pa1 = *reinterpret_cast<const uint4*>(_As + (size_t)(m0 + r + 64) * K + _kk + c16 * 8);  \
        pb0 = *reinterpret_cast<const uint4*>(_Bs + (size_t)(n0 + r) * K + _kk + c16 * 8);       \
        pb1 = *reinterpret_cast<const uint4*>(_Bs + (size_t)(n0 + r + 64) * K + _kk + c16 * 8);  \
    } while (0)

#define STS_CHUNK(buf) do {                                                   \
        *reinterpret_cast<uint4*>(&sA[buf][r * ROWE + c16 * 8]) = pa0;        \
        *reinterpret_cast<uint4*>(&sA[buf][(r + 64) * ROWE + c16 * 8]) = pa1; \
        *reinterpret_cast<uint4*>(&sB[buf][r * ROWE + c16 * 8]) = pb0;        \
        *reinterpret_cast<uint4*>(&sB[buf][(r + 64) * ROWE + c16 * 8]) = pb1; \
    } while (0)

    float cfr[4][4][4] = {};            // [mi][ng][reg]

    LDG_CHUNK(0);
    STS_CHUNK(0);
    if (total > 1) LDG_CHUNK(1);
    __syncthreads();

    for (int c = 0; c < total; c++) {
        const int buf = c & 1;
#pragma unroll
        for (int ks = 0; ks < 2; ks++) {
            const int kc = ks * 16 + tig * 2;
            uint32_t afr[4][4];
#pragma unroll
            for (int mi = 0; mi < 4; mi++) {
                int ar = warp_m * 64 + mi * 16 + gid;
                afr[mi][0] = *reinterpret_cast<const uint32_t*>(&sA[buf][ar * ROWE + kc]);
                afr[mi][1] = *reinterpret_cast<const uint32_t*>(&sA[buf][(ar + 8) * ROWE + kc]);
                afr[mi][2] = *reinterpret_cast<const uint32_t*>(&sA[buf][ar * ROWE + kc + 8]);
                afr[mi][3] = *reinterpret_cast<const uint32_t*>(&sA[buf][(ar + 8) * ROWE + kc + 8]);
            }
            uint32_t b0[4], b1[4];
#pragma unroll
            for (int ng = 0; ng < 4; ng++) {
                int br = warp_n * 32 + ng * 8 + gid;
                b0[ng] = *reinterpret_cast<const uint32_t*>(&sB[buf][br * ROWE + kc]);
                b1[ng] = *reinterpret_cast<const uint32_t*>(&sB[buf][br * ROWE + kc + 8]);
            }
#pragma unroll
            for (int mi = 0; mi < 4; mi++)
#pragma unroll
                for (int ng = 0; ng < 4; ng++)
                    mma16816(cfr[mi][ng], afr[mi], b0[ng], b1[ng]);
        }
        if (c + 1 < total) {
            __syncthreads();
            STS_CHUNK((c + 1) & 1);
            if (c + 2 < total) LDG_CHUNK(c + 2);
            __syncthreads();
        }
    }
#undef LDG_CHUNK
#undef STS_CHUNK

    // ---- epilogue (scalar stores only) ----
#pragma unroll
    for (int mi = 0; mi < 4; mi++) {
#pragma unroll
        for (int hh = 0; hh < 2; hh++) {
            int row = m0 + warp_m * 64 + mi * 16 + gid + hh * 8;
#pragma unroll
            for (int ng = 0; ng < 4; ng++) {
                int col = n0 + warp_n * 32 + ng * 8 + tig * 2;
                float v0 = cfr[mi][ng][hh * 2 + 0];
                float v1 = cfr[mi][ng][hh * 2 + 1];
                if (MODE == 0) {
                    int b = row >> 8, t = row & 255;
                    int hd = col >> 13, i = col & 8191;
                    size_t xi = ((size_t)((b << 2) + hd) * 256 + t) * 8192 + i;
                    float xe = fmaxf(v0, 0.f), xo = fmaxf(v1, 0.f);
                    g_x[xi] = xe; g_x[xi + 1] = xo;
                    int ci = t * 4096 + (i >> 1);
                    float cc = g_cos[ci], ss = g_sin[ci];
                    float re = xe * cc - xo * ss;
                    float ro = xo * cc + xe * ss;
                    __nv_bfloat16 h0, l0, h1, l1;
                    bf16split(re, h0, l0); bf16split(ro, h1, l1);
                    xr_h[xi] = h0; xr_h[xi + 1] = h1;
                    xr_l[xi] = l0; xr_l[xi + 1] = l1;
                } else if (MODE == 1) {
                    int b = row >> 8, t = row & 255;
                    int hd = col >> 13, i = col & 8191;
                    size_t xi = ((size_t)((b << 2) + hd) * 256 + t) * 8192 + i;
                    float y0 = fmaxf(v0, 0.f) * g_x[xi];
                    float y1 = fmaxf(v1, 0.f) * g_x[xi + 1];
                    size_t yi = (size_t)row * 32768 + col;
                    __nv_bfloat16 h0, l0, h1, l1;
                    bf16split(y0, h0, l0); bf16split(y1, h1, l1);
                    y_h[yi] = h0; y_h[yi + 1] = h1;
                    y_l[yi] = l0; y_l[yi + 1] = l1;
                } else if (MODE == 2) {
                    size_t ob = (((size_t)blockIdx.z * 8 + blockIdx.y) * 256 + row) * 256 + col;
                    g_sparts[ob] = v0; g_sparts[ob + 1] = v1;
                } else if (MODE == 3) {
                    size_t ob = ((size_t)blockIdx.z * 512 + row) * 256 + col;
                    g_kparts[ob] = v0; g_kparts[ob + 1] = v1;
                } else {
                    size_t ob = (size_t)row * 32000 + col;
                    outp[ob] = v0; outp[ob + 1] = v1;
                }
            }
        }
    }
}

// ------------------------- host launcher -----------------------------------
extern "C" void kernel_launch(void* const* d_in, const int* in_sizes, int n_in,
                              void* d_out, int out_size) {
    const int*   idx  = (const int*)d_in[0];
    const float* wte  = (const float*)d_in[1];
    const float* enc  = (const float*)d_in[2];
    const float* decx = (const float*)d_in[3];
    const float* decy = (const float*)d_in[4];
    const float* ro   = (const float*)d_in[5];
    float* out = (float*)d_out;
    (void)in_sizes; (void)n_in; (void)out_size;

    k_rope_table<<<4096, 256>>>();
    // weight transpose + bf16 hi/lo (destinations selected in-kernel!)
    k_tcvt<0><<<dim3(256, 8, 4), dim3(32, 8)>>>(decx, 256, 8192,
                                                (size_t)256 * 8192, (size_t)8192 * 256);
    k_tcvt<1><<<dim3(256, 8, 4), dim3(32, 8)>>>(decy, 256, 8192,
                                                (size_t)256 * 8192, (size_t)8192 * 256);
    k_tcvt<2><<<dim3(8, 1024, 1), dim3(32, 8)>>>(enc, 32768, 256, 0, 0);
    k_tcvt<3><<<dim3(1000, 8, 1), dim3(32, 8)>>>(ro, 256, 32000, 0, 0);
    k_embed<<<512, 256>>>(idx, wte);

    for (int l = 0; l < LAYERS; l++) {
        k_mma<0><<<dim3(256, 4), 256>>>(nullptr);   // x + rope
        k_mma<2><<<dim3(3, 8, 8), 256>>>(nullptr);  // score partials
        k_softmax<<<512, 256>>>();                  // P
        k_pv<<<dim3(4, 4, 2), 256>>>();             // a = P @ v
        k_ln_a<<<512, 256>>>();                     // lna hi/lo
        k_mma<1><<<dim3(256, 4), 256>>>(nullptr);   // y hi/lo
        k_mma<3><<<dim3(2, 4, 32), 256>>>(nullptr); // enc partials
        k_reduce<<<512, 256>>>();                   // z
        k_residual<<<512, 256>>>();                 // v = ln(v+ln(z))
    }

    k_mma<4><<<dim3(250, 4), 256>>>(out);           // logits
}

// round 9
// speedup vs baseline: 2.2147x; 1.0754x over previous
#include <cuda_runtime.h>
#include <cuda_bf16.h>
#include <math.h>
#include <stdint.h>

// ---------------------------------------------------------------------------
// BDH forward. GEMMs = bf16 hi/lo 3-combo MERGED-PASS warp-tiled HMMA.
// Per k-chunk: load Ah,Al,Bh,Bl tiles once, accumulate hi*hi + hi*lo + lo*hi.
// B=2,T=256,D=256,H=4,n=8192,N=32768,V=32000,L=6
// ---------------------------------------------------------------------------
#define LAYERS 6
#define LN_EPS 1e-5f
#define SCALE_ATTN 0.011048543456039806f   // 1/sqrt(8192)

#define ROWE 40                 // smem row stride in bf16 elements (80 bytes)

__device__ __forceinline__ void mma16816(float d[4], const uint32_t a[4],
                                         uint32_t b0, uint32_t b1) {
    asm volatile(
        "mma.sync.aligned.m16n8k16.row.col.f32.bf16.bf16.f32 "
        "{%0,%1,%2,%3}, {%4,%5,%6,%7}, {%8,%9}, {%0,%1,%2,%3};"
        : "+f"(d[0]), "+f"(d[1]), "+f"(d[2]), "+f"(d[3])
        : "r"(a[0]), "r"(a[1]), "r"(a[2]), "r"(a[3]), "r"(b0), "r"(b1));
}

// ------------------------- device globals ----------------------------------
__device__ float g_v[512*256];
__device__ __align__(16) float g_x[(size_t)8*256*8192];   // (b*4+h, t, i)
__device__ float g_cos[256*4096];
__device__ float g_sin[256*4096];
__device__ __align__(16) float g_sparts[(size_t)16*8*256*256];  // 16 splits
__device__ float g_P[2*256*256];
__device__ float g_a[512*256];
__device__ __align__(16) float g_kparts[(size_t)32*512*256];
__device__ float g_z[512*256];

__device__ __align__(16) __nv_bfloat16 v_h[512*256],   v_l[512*256];
__device__ __align__(16) __nv_bfloat16 lna_h[512*256], lna_l[512*256];
__device__ __align__(16) __nv_bfloat16 xr_h[(size_t)8*256*8192];
__device__ __align__(16) __nv_bfloat16 xr_l[(size_t)8*256*8192];
__device__ __align__(16) __nv_bfloat16 y_h[(size_t)512*32768];
__device__ __align__(16) __nv_bfloat16 y_l[(size_t)512*32768];
__device__ __align__(16) __nv_bfloat16 dxt_h[(size_t)32768*256];
__device__ __align__(16) __nv_bfloat16 dxt_l[(size_t)32768*256];
__device__ __align__(16) __nv_bfloat16 dyt_h[(size_t)32768*256];
__device__ __align__(16) __nv_bfloat16 dyt_l[(size_t)32768*256];
__device__ __align__(16) __nv_bfloat16 et_h[(size_t)256*32768];
__device__ __align__(16) __nv_bfloat16 et_l[(size_t)256*32768];
__device__ __align__(16) __nv_bfloat16 rt_h[(size_t)32000*256];
__device__ __align__(16) __nv_bfloat16 rt_l[(size_t)32000*256];

__device__ __forceinline__ void bf16split(float v, __nv_bfloat16& h, __nv_bfloat16& l) {
    h = __float2bfloat16(v);
    l = __float2bfloat16(v - __bfloat162float(h));
}

// ------------------------- block reductions --------------------------------
__device__ __forceinline__ float blk_sum256(float v, float* sh) {
#pragma unroll
    for (int o = 16; o > 0; o >>= 1) v += __shfl_xor_sync(0xffffffffu, v, o);
    if ((threadIdx.x & 31) == 0) sh[threadIdx.x >> 5] = v;
    __syncthreads();
    float tot = 0.f;
#pragma unroll
    for (int w = 0; w < 8; w++) tot += sh[w];
    __syncthreads();
    return tot;
}
__device__ __forceinline__ float blk_max256(float v, float* sh) {
#pragma unroll
    for (int o = 16; o > 0; o >>= 1) v = fmaxf(v, __shfl_xor_sync(0xffffffffu, v, o));
    if ((threadIdx.x & 31) == 0) sh[threadIdx.x >> 5] = v;
    __syncthreads();
    float tot = -3.0e38f;
#pragma unroll
    for (int w = 0; w < 8; w++) tot = fmaxf(tot, sh[w]);
    __syncthreads();
    return tot;
}
__device__ __forceinline__ float ln_elem(float x, float* sh) {
    float mean = blk_sum256(x, sh) * (1.f / 256.f);
    float d = x - mean;
    float var = blk_sum256(d * d, sh) * (1.f / 256.f);
    return d * rsqrtf(var + LN_EPS);
}

// ------------------------- small kernels -----------------------------------
__global__ void k_rope_table() {
    int idx = blockIdx.x * 256 + threadIdx.x;
    int i = idx & 4095;
    int t = idx >> 12;
    float ex = (float)(2 * i) * (1.0f / 8192.0f);
    float inv = expf(-9.210340371976184f * ex);
    float f = (float)t * inv;
    float s, c;
    sincosf(f, &s, &c);
    g_cos[idx] = c;
    g_sin[idx] = s;
}

__global__ void k_embed(const int* __restrict__ idx, const float* __restrict__ wte) {
    __shared__ float sh[8];
    int row = blockIdx.x, tid = threadIdx.x;
    int tok = idx[row];
    float x = wte[(size_t)tok * 256 + tid];
    float r = ln_elem(x, sh);
    g_v[row * 256 + tid] = r;
    __nv_bfloat16 h, l; bf16split(r, h, l);
    v_h[row * 256 + tid] = h; v_l[row * 256 + tid] = l;
}

// transpose + bf16 hi/lo: out[c*R + r] = in[r*C + c]; DST selected in-kernel.
template<int DST>
__global__ void k_tcvt(const float* __restrict__ in, int R, int C,
                       size_t in_z, size_t out_z) {
    __shared__ float tile[32][33];
    __nv_bfloat16* oh;
    __nv_bfloat16* ol;
    if (DST == 0) { oh = dxt_h; ol = dxt_l; }
    else if (DST == 1) { oh = dyt_h; ol = dyt_l; }
    else if (DST == 2) { oh = et_h; ol = et_l; }
    else { oh = rt_h; ol = rt_l; }
    int z = blockIdx.z;
    const float* src = in + (size_t)z * in_z;
    __nv_bfloat16* dh = oh + (size_t)z * out_z;
    __nv_bfloat16* dl = ol + (size_t)z * out_z;
    int r0 = blockIdx.y * 32, c0 = blockIdx.x * 32;
    for (int i = threadIdx.y; i < 32; i += 8)
        tile[i][threadIdx.x] = src[(size_t)(r0 + i) * C + c0 + threadIdx.x];
    __syncthreads();
    for (int i = threadIdx.y; i < 32; i += 8) {
        float v = tile[threadIdx.x][i];
        __nv_bfloat16 h, l; bf16split(v, h, l);
        size_t o = (size_t)(c0 + i) * R + r0 + threadIdx.x;
        dh[o] = h; dl[o] = l;
    }
}

__global__ void k_softmax() {
    __shared__ float sh[8];
    int row = blockIdx.x;
    int b = row >> 8, t = row & 255;
    int s = threadIdx.x;
    float pacc = 0.f;
    for (int h = 0; h < 4; h++) {
        float val = -3.0e38f;
        if (s <= t) {
            float sum = 0.f;
            int bh = b * 4 + h;
#pragma unroll
            for (int sp = 0; sp < 16; sp++)
                sum += g_sparts[(((size_t)sp * 8 + bh) * 256 + t) * 256 + s];
            val = sum * SCALE_ATTN;
        }
        float mx = blk_max256(val, sh);
        float e = (s <= t) ? expf(val - mx) : 0.f;
        float ssum = blk_sum256(e, sh);
        pacc += e / ssum;
    }
    g_P[(size_t)row * 256 + s] = pacc * 0.25f;
}

// ---- fp32 SIMT tile GEMM kept for tiny P@V ----
__device__ __forceinline__ void load_tile_T(float dst[16][68], const float* __restrict__ src,
                                            int lda, int tid) {
    int m = tid >> 2, ks = (tid & 3) << 2;
    float4 v = *reinterpret_cast<const float4*>(src + (size_t)m * lda + ks);
    dst[ks + 0][m] = v.x; dst[ks + 1][m] = v.y; dst[ks + 2][m] = v.z; dst[ks + 3][m] = v.w;
}
__device__ __forceinline__ void load_tile_N(float dst[16][68], const float* __restrict__ src,
                                            int ldb, int tid) {
    int j = tid & 63, k0 = (tid >> 6) << 2;
#pragma unroll
    for (int u = 0; u < 4; u++) dst[k0 + u][j] = src[(size_t)(k0 + u) * ldb + j];
}
__device__ __forceinline__ void mm_tile(const float As[16][68], const float Bs[16][68],
                                        float acc[4][4], int ty, int tx) {
#pragma unroll
    for (int k = 0; k < 16; k++) {
        float4 a = *reinterpret_cast<const float4*>(&As[k][ty << 2]);
        float4 b = *reinterpret_cast<const float4*>(&Bs[k][tx << 2]);
        float av[4] = {a.x, a.y, a.z, a.w};
        float bv[4] = {b.x, b.y, b.z, b.w};
#pragma unroll
        for (int r = 0; r < 4; r++)
#pragma unroll
            for (int c = 0; c < 4; c++) acc[r][c] = fmaf(av[r], bv[c], acc[r][c]);
    }
}
__global__ void __launch_bounds__(256) k_pv() {
    __shared__ float As[16][68], Bs[16][68];
    int tid = threadIdx.x, tx = tid & 15, ty = tid >> 4;
    int col0 = blockIdx.x << 6, row0 = blockIdx.y << 6, b = blockIdx.z;
    const float* A  = g_P + (size_t)b * 65536;
    const float* Bv = g_v + (size_t)b * 65536;
    float acc[4][4] = {};
    for (int kk = 0; kk < 256; kk += 16) {
        load_tile_T(As, A + (size_t)row0 * 256 + kk, 256, tid);
        load_tile_N(Bs, Bv + (size_t)kk * 256 + col0, 256, tid);
        __syncthreads();
        mm_tile(As, Bs, acc, ty, tx);
        __syncthreads();
    }
#pragma unroll
    for (int r = 0; r < 4; r++) {
        size_t ob = ((size_t)b * 256 + row0 + (ty << 2) + r) * 256 + col0 + (tx << 2);
#pragma unroll
        for (int c = 0; c < 4; c++) g_a[ob + c] = acc[r][c];
    }
}

__global__ void k_ln_a() {
    __shared__ float sh[8];
    int row = blockIdx.x, tid = threadIdx.x;
    float x = g_a[row * 256 + tid];
    float r = ln_elem(x, sh);
    __nv_bfloat16 h, l; bf16split(r, h, l);
    lna_h[row * 256 + tid] = h; lna_l[row * 256 + tid] = l;
}

__global__ void k_reduce() {
    int i = blockIdx.x * 256 + threadIdx.x;
    float s = 0.f;
#pragma unroll
    for (int sp = 0; sp < 32; sp++) s += g_kparts[(size_t)sp * 131072 + i];
    g_z[i] = s;
}

__global__ void k_residual() {
    __shared__ float sh[8];
    int row = blockIdx.x, tid = threadIdx.x;
    float z = g_z[row * 256 + tid];
    float lnz = ln_elem(z, sh);
    float t = g_v[row * 256 + tid] + lnz;
    float r = ln_elem(t, sh);
    g_v[row * 256 + tid] = r;
    __nv_bfloat16 h, l; bf16split(r, h, l);
    v_h[row * 256 + tid] = h; v_l[row * 256 + tid] = l;
}

// ------------------------- HMMA GEMM (merged-pass engine) -------------------
// MODE: 0=dec-x (relu -> g_x + fused rope -> xr hi/lo)
//       1=dec-y (relu * g_x -> y hi/lo)
//       2=scores (fp32 -> g_sparts, 16 splits)
//       3=enc (fp32 -> g_kparts)   4=readout (fp32 -> out)
// 128x128 tile, BK=32 (2 k-steps), 8 warps (2m x 4n), warp tile 64x32.
// Per chunk: Ah,Al,Bh,Bl in smem; cfr += Ah*Bh + Ah*Bl + Al*Bh.
template<int MODE>
__global__ void __launch_bounds__(256) k_mma(float* __restrict__ outp) {
    __shared__ __align__(16) __nv_bfloat16 sAh[128 * ROWE];
    __shared__ __align__(16) __nv_bfloat16 sAl[128 * ROWE];
    __shared__ __align__(16) __nv_bfloat16 sBh[128 * ROWE];
    __shared__ __align__(16) __nv_bfloat16 sBl[128 * ROWE];

    int tid = threadIdx.x;
    int wid = tid >> 5, lane = tid & 31;
    int warp_m = wid & 1, warp_n = wid >> 1;
    int gid = lane >> 2, tig = lane & 3;

    const __nv_bfloat16 *Ah, *Al, *Bh, *Bl;
    size_t K;
    int m0, n0, k0, klen;
    if (MODE == 0) {
        Ah = v_h; Al = v_l; Bh = dxt_h; Bl = dxt_l;
        K = 256; m0 = blockIdx.y << 7; n0 = blockIdx.x << 7; k0 = 0; klen = 256;
    } else if (MODE == 1) {
        Ah = lna_h; Al = lna_l; Bh = dyt_h; Bl = dyt_l;
        K = 256; m0 = blockIdx.y << 7; n0 = blockIdx.x << 7; k0 = 0; klen = 256;
    } else if (MODE == 2) {
        size_t off = (size_t)blockIdx.y * 256 * 8192;
        Ah = xr_h + off; Al = xr_l + off; Bh = Ah; Bl = Al;
        K = 8192;
        int tp = blockIdx.x;
        m0 = ((tp + 1) >> 1) << 7; n0 = (tp >> 1) << 7;
        k0 = blockIdx.z << 9; klen = 512;
    } else if (MODE == 3) {
        Ah = y_h; Al = y_l; Bh = et_h; Bl = et_l;
        K = 32768; m0 = blockIdx.y << 7; n0 = blockIdx.x << 7;
        k0 = blockIdx.z << 10; klen = 1024;
    } else {
        Ah = v_h; Al = v_l; Bh = rt_h; Bl = rt_l;
        K = 256; m0 = blockIdx.y << 7; n0 = blockIdx.x << 7; k0 = 0; klen = 256;
    }

    const int total = klen >> 5;        // 32-k chunks (single merged sweep)

    // per-thread LDG/STS geometry: rows r and r+64, 16B column chunk c16
    const int r = tid >> 2, c16 = tid & 3;
    uint4 pah0, pah1, pal0, pal1, pbh0, pbh1, pbl0, pbl1;

#define LDG_CHUNK(c) do {                                                     \
        int _kk = k0 + ((c) << 5);                                            \
        pah0 = *reinterpret_cast<const uint4*>(Ah + (size_t)(m0 + r) * K + _kk + c16 * 8);       \
        pah1 = *reinterpret_cast<const uint4*>(Ah + (size_t)(m0 + r + 64) * K + _kk + c16 * 8);  \
        pal0 = *reinterpret_cast<const uint4*>(Al + (size_t)(m0 + r) * K + _kk + c16 * 8);       \
        pal1 = *reinterpret_cast<const uint4*>(Al + (size_t)(m0 + r + 64) * K + _kk + c16 * 8);  \
        pbh0 = *reinterpret_cast<const uint4*>(Bh + (size_t)(n0 + r) * K + _kk + c16 * 8);       \
        pbh1 = *reinterpret_cast<const uint4*>(Bh + (size_t)(n0 + r + 64) * K + _kk + c16 * 8);  \
        pbl0 = *reinterpret_cast<const uint4*>(Bl + (size_t)(n0 + r) * K + _kk + c16 * 8);       \
        pbl1 = *reinterpret_cast<const uint4*>(Bl + (size_t)(n0 + r + 64) * K + _kk + c16 * 8);  \
    } while (0)

#define STS_CHUNK() do {                                                      \
        *reinterpret_cast<uint4*>(&sAh[r * ROWE + c16 * 8]) = pah0;           \
        *reinterpret_cast<uint4*>(&sAh[(r + 64) * ROWE + c16 * 8]) = pah1;    \
        *reinterpret_cast<uint4*>(&sAl[r * ROWE + c16 * 8]) = pal0;           \
        *reinterpret_cast<uint4*>(&sAl[(r + 64) * ROWE + c16 * 8]) = pal1;    \
        *reinterpret_cast<uint4*>(&sBh[r * ROWE + c16 * 8]) = pbh0;           \
        *reinterpret_cast<uint4*>(&sBh[(r + 64) * ROWE + c16 * 8]) = pbh1;    \
        *reinterpret_cast<uint4*>(&sBl[r * ROWE + c16 * 8]) = pbl0;           \
        *reinterpret_cast<uint4*>(&sBl[(r + 64) * ROWE + c16 * 8]) = pbl1;    \
    } while (0)

    float cfr[4][4][4] = {};            // [mi][ng][reg]

    LDG_CHUNK(0);
    STS_CHUNK();
    if (total > 1) LDG_CHUNK(1);
    __syncthreads();

    for (int c = 0; c < total; c++) {
#pragma unroll
        for (int ks = 0; ks < 2; ks++) {
            const int kc = ks * 16 + tig * 2;
            uint32_t af[4][4];
            uint32_t b0[4], b1[4];
            // --- A-hi fragments ---
#pragma unroll
            for (int mi = 0; mi < 4; mi++) {
                int ar = warp_m * 64 + mi * 16 + gid;
                af[mi][0] = *reinterpret_cast<const uint32_t*>(&sAh[ar * ROWE + kc]);
                af[mi][1] = *reinterpret_cast<const uint32_t*>(&sAh[(ar + 8) * ROWE + kc]);
                af[mi][2] = *reinterpret_cast<const uint32_t*>(&sAh[ar * ROWE + kc + 8]);
                af[mi][3] = *reinterpret_cast<const uint32_t*>(&sAh[(ar + 8) * ROWE + kc + 8]);
            }
            // --- B-hi fragments, combo hi*hi ---
#pragma unroll
            for (int ng = 0; ng < 4; ng++) {
                int br = warp_n * 32 + ng * 8 + gid;
                b0[ng] = *reinterpret_cast<const uint32_t*>(&sBh[br * ROWE + kc]);
                b1[ng] = *reinterpret_cast<const uint32_t*>(&sBh[br * ROWE + kc + 8]);
            }
#pragma unroll
            for (int mi = 0; mi < 4; mi++)
#pragma unroll
                for (int ng = 0; ng < 4; ng++)
                    mma16816(cfr[mi][ng], af[mi], b0[ng], b1[ng]);
            // --- B-lo fragments, combo hi*lo ---
#pragma unroll
            for (int ng = 0; ng < 4; ng++) {
                int br = warp_n * 32 + ng * 8 + gid;
                b0[ng] = *reinterpret_cast<const uint32_t*>(&sBl[br * ROWE + kc]);
                b1[ng] = *reinterpret_cast<const uint32_t*>(&sBl[br * ROWE + kc + 8]);
            }
#pragma unroll
            for (int mi = 0; mi < 4; mi++)
#pragma unroll
                for (int ng = 0; ng < 4; ng++)
                    mma16816(cfr[mi][ng], af[mi], b0[ng], b1[ng]);
            // --- A-lo fragments + reload B-hi, combo lo*hi ---
#pragma unroll
            for (int mi = 0; mi < 4; mi++) {
                int ar = warp_m * 64 + mi * 16 + gid;
                af[mi][0] = *reinterpret_cast<const uint32_t*>(&sAl[ar * ROWE + kc]);
                af[mi][1] = *reinterpret_cast<const uint32_t*>(&sAl[(ar + 8) * ROWE + kc]);
                af[mi][2] = *reinterpret_cast<const uint32_t*>(&sAl[ar * ROWE + kc + 8]);
                af[mi][3] = *reinterpret_cast<const uint32_t*>(&sAl[(ar + 8) * ROWE + kc + 8]);
            }
#pragma unroll
            for (int ng = 0; ng < 4; ng++) {
                int br = warp_n * 32 + ng * 8 + gid;
                b0[ng] = *reinterpret_cast<const uint32_t*>(&sBh[br * ROWE + kc]);
                b1[ng] = *reinterpret_cast<const uint32_t*>(&sBh[br * ROWE + kc + 8]);
            }
#pragma unroll
            for (int mi = 0; mi < 4; mi++)
#pragma unroll
                for (int ng = 0; ng < 4; ng++)
                    mma16816(cfr[mi][ng], af[mi], b0[ng], b1[ng]);
        }
        if (c + 1 < total) {
            __syncthreads();
            STS_CHUNK();
            if (c + 2 < total) LDG_CHUNK(c + 2);
            __syncthreads();
        }
    }
#undef LDG_CHUNK
#undef STS_CHUNK

    // ---- epilogue (scalar stores only) ----
#pragma unroll
    for (int mi = 0; mi < 4; mi++) {
#pragma unroll
        for (int hh = 0; hh < 2; hh++) {
            int row = m0 + warp_m * 64 + mi * 16 + gid + hh * 8;
#pragma unroll
            for (int ng = 0; ng < 4; ng++) {
                int col = n0 + warp_n * 32 + ng * 8 + tig * 2;
                float v0 = cfr[mi][ng][hh * 2 + 0];
                float v1 = cfr[mi][ng][hh * 2 + 1];
                if (MODE == 0) {
                    int b = row >> 8, t = row & 255;
                    int hd = col >> 13, i = col & 8191;
                    size_t xi = ((size_t)((b << 2) + hd) * 256 + t) * 8192 + i;
                    float xe = fmaxf(v0, 0.f), xo = fmaxf(v1, 0.f);
                    g_x[xi] = xe; g_x[xi + 1] = xo;
                    int ci = t * 4096 + (i >> 1);
                    float cc = g_cos[ci], ss = g_sin[ci];
                    float re = xe * cc - xo * ss;
                    float ro = xo * cc + xe * ss;
                    __nv_bfloat16 h0, l0, h1, l1;
                    bf16split(re, h0, l0); bf16split(ro, h1, l1);
                    xr_h[xi] = h0; xr_h[xi + 1] = h1;
                    xr_l[xi] = l0; xr_l[xi + 1] = l1;
                } else if (MODE == 1) {
                    int b = row >> 8, t = row & 255;
                    int hd = col >> 13, i = col & 8191;
                    size_t xi = ((size_t)((b << 2) + hd) * 256 + t) * 8192 + i;
                    float y0 = fmaxf(v0, 0.f) * g_x[xi];
                    float y1 = fmaxf(v1, 0.f) * g_x[xi + 1];
                    size_t yi = (size_t)row * 32768 + col;
                    __nv_bfloat16 h0, l0, h1, l1;
                    bf16split(y0, h0, l0); bf16split(y1, h1, l1);
                    y_h[yi] = h0; y_h[yi + 1] = h1;
                    y_l[yi] = l0; y_l[yi + 1] = l1;
                } else if (MODE == 2) {
                    size_t ob = (((size_t)blockIdx.z * 8 + blockIdx.y) * 256 + row) * 256 + col;
                    g_sparts[ob] = v0; g_sparts[ob + 1] = v1;
                } else if (MODE == 3) {
                    size_t ob = ((size_t)blockIdx.z * 512 + row) * 256 + col;
                    g_kparts[ob] = v0; g_kparts[ob + 1] = v1;
                } else {
                    size_t ob = (size_t)row * 32000 + col;
                    outp[ob] = v0; outp[ob + 1] = v1;
                }
            }
        }
    }
}

// ------------------------- host launcher -----------------------------------
extern "C" void kernel_launch(void* const* d_in, const int* in_sizes, int n_in,
                              void* d_out, int out_size) {
    const int*   idx  = (const int*)d_in[0];
    const float* wte  = (const float*)d_in[1];
    const float* enc  = (const float*)d_in[2];
    const float* decx = (const float*)d_in[3];
    const float* decy = (const float*)d_in[4];
    const float* ro   = (const float*)d_in[5];
    float* out = (float*)d_out;
    (void)in_sizes; (void)n_in; (void)out_size;

    k_rope_table<<<4096, 256>>>();
    k_tcvt<0><<<dim3(256, 8, 4), dim3(32, 8)>>>(decx, 256, 8192,
                                                (size_t)256 * 8192, (size_t)8192 * 256);
    k_tcvt<1><<<dim3(256, 8, 4), dim3(32, 8)>>>(decy, 256, 8192,
                                                (size_t)256 * 8192, (size_t)8192 * 256);
    k_tcvt<2><<<dim3(8, 1024, 1), dim3(32, 8)>>>(enc, 32768, 256, 0, 0);
    k_tcvt<3><<<dim3(1000, 8, 1), dim3(32, 8)>>>(ro, 256, 32000, 0, 0);
    k_embed<<<512, 256>>>(idx, wte);

    for (int l = 0; l < LAYERS; l++) {
        k_mma<0><<<dim3(256, 4), 256>>>(nullptr);    // x + rope
        k_mma<2><<<dim3(3, 8, 16), 256>>>(nullptr);  // score partials (16 splits)
        k_softmax<<<512, 256>>>();                   // P
        k_pv<<<dim3(4, 4, 2), 256>>>();              // a = P @ v
        k_ln_a<<<512, 256>>>();                      // lna hi/lo
        k_mma<1><<<dim3(256, 4), 256>>>(nullptr);    // y hi/lo
        k_mma<3><<<dim3(2, 4, 32), 256>>>(nullptr);  // enc partials
        k_reduce<<<512, 256>>>();                    // z
        k_residual<<<512, 256>>>();                  // v = ln(v+ln(z))
    }

    k_mma<4><<<dim3(250, 4), 256>>>(out);            // logits
}